// round 11
// baseline (speedup 1.0000x reference)
#include <cuda_runtime.h>
#include <math.h>

// Problem constants
#define Bq   4
#define Nn   512
#define Tt   24
#define NXf  8
#define Hh   64
#define PL   12
#define MAXD 128
#define MROWS (Bq*Nn)            // 2048 (b,n) rows
#define XROWS (Bq*Nn*Tt)         // 49152 (b,n,t) rows

// -------- scratch (device globals; no allocation allowed) --------
__device__ float    g_xh  [XROWS*Hh];        // x @ W_fc + b_fc, layout (b,n,t,h)
__device__ float    g_gx  [XROWS*4*Hh];      // precomputed input gates (row, 256)
__device__ float    g_hbuf[MROWS*Hh];        // GAT per-node features at t=T-1
__device__ float    g_el  [MROWS];
__device__ float    g_er  [MROWS];
__device__ float    g_g1  [MROWS*Hh];        // GAT layer-1 output (t=T-1 slice)
__device__ float    g_g2  [MROWS*Hh];        // GAT layer-2 output
__device__ float    g_lh  [MROWS*Hh];        // final LSTM hidden
__device__ unsigned g_bm  [Nn*16];           // adjacency bitmask (512 x 512 bits)
__device__ int      g_deg [Nn];
__device__ int      g_nbr [Nn*MAXD];

__device__ __forceinline__ float wsum(float v){
#pragma unroll
    for (int o = 16; o; o >>= 1) v += __shfl_xor_sync(0xffffffffu, v, o);
    return v;
}
__device__ __forceinline__ float wmax(float v){
#pragma unroll
    for (int o = 16; o; o >>= 1) v = fmaxf(v, __shfl_xor_sync(0xffffffffu, v, o));
    return v;
}
__device__ __forceinline__ float sigf(float x){ return 1.f / (1.f + __expf(-x)); }
__device__ __forceinline__ float tanhacc(float x){
    float e = __expf(2.f * x);
    return (e - 1.f) / (e + 1.f);
}

// -------- K0: zero bitmask --------
__global__ void k_zero(){
    int i = blockIdx.x * 512 + threadIdx.x;
    if (i < Nn*16) g_bm[i] = 0u;
}

// -------- K1: scatter edges into bitmask (dedup via OR) --------
__global__ void k_scatter(const int* __restrict__ ei, int E){
    int i = blockIdx.x * 256 + threadIdx.x;
    if (i >= E) return;
    int r = ei[i], c = ei[E + i];
    atomicOr(&g_bm[r*16 + (c >> 5)], 1u << (c & 31));
}

// -------- K2: bitmask -> compact neighbor lists --------
__global__ void k_nbr(){
    int m = blockIdx.x * 256 + threadIdx.x;
    if (m >= Nn) return;
    int cnt = 0;
#pragma unroll
    for (int w = 0; w < 16; w++){
        unsigned word = g_bm[m*16 + w];
        while (word){
            int b = __ffs(word) - 1;
            word &= word - 1;
            if (cnt < MAXD) g_nbr[m*MAXD + cnt] = w*32 + b;
            cnt++;
        }
    }
    g_deg[m] = cnt < MAXD ? cnt : MAXD;
}

// -------- K3: x_h = x @ W_fc + b_fc (warp per (b,n,t) row) --------
__global__ void k_xh(const float* __restrict__ x, const float* __restrict__ Wfc,
                     const float* __restrict__ bfc){
    __shared__ float wsm[NXf*Hh];
    __shared__ float bsm[Hh];
    int tid = threadIdx.x;
    for (int i = tid; i < NXf*Hh; i += 256) wsm[i] = Wfc[i];
    if (tid < Hh) bsm[tid] = bfc[tid];
    __syncthreads();
    int row  = (blockIdx.x * 256 + tid) >> 5;   // exact: 6144 blocks * 8 warps = 49152
    int lane = tid & 31;
    float xv = lane < NXf ? x[row*NXf + lane] : 0.f;
    float a0 = bsm[lane], a1 = bsm[lane + 32];
#pragma unroll
    for (int f = 0; f < NXf; f++){
        float v = __shfl_sync(0xffffffffu, xv, f);
        a0 = fmaf(v, wsm[f*Hh + lane],      a0);
        a1 = fmaf(v, wsm[f*Hh + lane + 32], a1);
    }
    g_xh[row*Hh + lane]      = a0;
    g_xh[row*Hh + lane + 32] = a1;
}

// -------- K4: GAT node transform at t=T-1: h = x @ W, el/er dots --------
__global__ void k_gat_h(const float* __restrict__ W, const float* __restrict__ al,
                        const float* __restrict__ ar, int layer){
    __shared__ float wsm[Hh*Hh];
    int tid = threadIdx.x;
    for (int i = tid; i < Hh*Hh; i += 256) wsm[i] = W[i];
    __syncthreads();
    int r    = (blockIdx.x * 256 + tid) >> 5;   // 0..2047 exact
    int lane = tid & 31;
    const float* xr = (layer == 0)
        ? (g_xh + (size_t)r * (Tt*Hh) + (Tt-1)*Hh)   // x_h[b,n,T-1,:]
        : (g_g1 + (size_t)r * Hh);                   // g1[b,n,T-1,:]
    float xa = xr[lane], xb = xr[lane + 32];
    float a0 = 0.f, a1 = 0.f;
#pragma unroll
    for (int f = 0; f < 32; f++){
        float v = __shfl_sync(0xffffffffu, xa, f);
        a0 = fmaf(v, wsm[f*Hh + lane],      a0);
        a1 = fmaf(v, wsm[f*Hh + lane + 32], a1);
    }
#pragma unroll
    for (int f = 0; f < 32; f++){
        float v = __shfl_sync(0xffffffffu, xb, f);
        a0 = fmaf(v, wsm[(f+32)*Hh + lane],      a0);
        a1 = fmaf(v, wsm[(f+32)*Hh + lane + 32], a1);
    }
    g_hbuf[r*Hh + lane]      = a0;
    g_hbuf[r*Hh + lane + 32] = a1;
    float pl = a0*al[lane] + a1*al[lane+32];
    float pr = a0*ar[lane] + a1*ar[lane+32];
    pl = wsum(pl); pr = wsum(pr);
    if (lane == 0){ g_el[r] = pl; g_er[r] = pr; }
}

// -------- K5: sparse GAT attention + aggregation + bias + exact GELU --------
__global__ void k_gat_agg(const float* __restrict__ bias, int layer){
    __shared__ float wbuf[8][MAXD];
    __shared__ int   nbuf[8][MAXD];
    int tid = threadIdx.x, lane = tid & 31, w = tid >> 5;
    int r = blockIdx.x * 8 + w;          // 0..2047
    int b = r >> 9, m = r & 511;
    int d = g_deg[m];
    float elm = g_el[r];
    float mx = -1e30f;
    for (int k = lane; k < d; k += 32){
        int n = g_nbr[m*MAXD + k];
        float e = elm + g_er[(b << 9) + n];
        e = e >= 0.f ? e : 0.2f * e;     // leaky_relu(0.2)
        wbuf[w][k] = e; nbuf[w][k] = n;
        mx = fmaxf(mx, e);
    }
    mx = wmax(mx);
    __syncwarp();
    float s = 0.f;
    for (int k = lane; k < d; k += 32){
        float wv = __expf(wbuf[w][k] - mx);
        wbuf[w][k] = wv; s += wv;
    }
    s = wsum(s);
    __syncwarp();
    float a0 = 0.f, a1 = 0.f;
    for (int k = 0; k < d; k++){
        float wv = wbuf[w][k];
        int   n  = nbuf[w][k];
        const float* hr = g_hbuf + ((size_t)((b << 9) + n)) * Hh;
        a0 = fmaf(wv, hr[lane],      a0);
        a1 = fmaf(wv, hr[lane + 32], a1);
    }
    float inv = 1.f / s;
    float v0 = a0*inv + bias[lane];
    float v1 = a1*inv + bias[lane+32];
    v0 = 0.5f * v0 * (1.f + erff(v0 * 0.70710678118654752f));   // exact gelu
    v1 = 0.5f * v1 * (1.f + erff(v1 * 0.70710678118654752f));
    float* out = layer ? g_g2 : g_g1;
    out[r*Hh + lane]      = v0;
    out[r*Hh + lane + 32] = v1;
}

// -------- K6: precompute input gates: gx = x_h @ W_ih^T + (b_ih + b_hh) ----
// 16 rows per block; thread g keeps W_ih[g][:] in registers; x broadcast smem.
__global__ void __launch_bounds__(256) k_gx(const float* __restrict__ Wih,
                                            const float* __restrict__ bih,
                                            const float* __restrict__ bhh){
    __shared__ float4 xs[16*16];   // 16 rows x 64 floats
    int tid  = threadIdx.x;        // = gate index g (0..255)
    int row0 = blockIdx.x * 16;
    xs[tid] = ((const float4*)(g_xh + (size_t)row0*Hh))[tid];
    float4 wreg[16];
#pragma unroll
    for (int j = 0; j < 16; j++) wreg[j] = ((const float4*)(Wih + tid*Hh))[j];
    float bsum = bih[tid] + bhh[tid];
    __syncthreads();
    float* gdst = g_gx + (size_t)row0*256 + tid;
#pragma unroll 4
    for (int rr = 0; rr < 16; rr++){
        const float4* xr = xs + rr*16;
        float ax = bsum, ay = 0.f, az = 0.f, aw = 0.f;
#pragma unroll
        for (int j = 0; j < 16; j++){
            float4 v = xr[j];
            ax = fmaf(v.x, wreg[j].x, ax);
            ay = fmaf(v.y, wreg[j].y, ay);
            az = fmaf(v.z, wreg[j].z, az);
            aw = fmaf(v.w, wreg[j].w, aw);
        }
        gdst[(size_t)rr*256] = (ax + ay) + (az + aw);
    }
}

// -------- K7: recurrent LSTM. 16 sequences per block, W_hh in registers ----
__global__ void __launch_bounds__(256) k_lstm(const float* __restrict__ Whh){
    __shared__ float4 hsm[16*16];      // 16 seq x 64 h
    __shared__ float  gsm[16*256];     // gate pre-activations
    int tid = threadIdx.x;             // = gate index g
    int s0  = blockIdx.x * 16;
    float4 wreg[16];
#pragma unroll
    for (int j = 0; j < 16; j++) wreg[j] = ((const float4*)(Whh + tid*Hh))[j];
    hsm[tid] = make_float4(0.f, 0.f, 0.f, 0.f);
    float c0 = 0.f, c1 = 0.f, c2 = 0.f, c3 = 0.f;
    __syncthreads();
    for (int t = 0; t < Tt; t++){
        const float* gxb = g_gx + ((size_t)s0*Tt + t)*256 + tid;
#pragma unroll 2
        for (int s = 0; s < 16; s++){
            const float4* hr = hsm + s*16;
            float ax = gxb[(size_t)s*Tt*256], ay = 0.f, az = 0.f, aw = 0.f;
#pragma unroll
            for (int j = 0; j < 16; j++){
                float4 v = hr[j];
                ax = fmaf(v.x, wreg[j].x, ax);
                ay = fmaf(v.y, wreg[j].y, ay);
                az = fmaf(v.z, wreg[j].z, az);
                aw = fmaf(v.w, wreg[j].w, aw);
            }
            gsm[s*256 + tid] = (ax + ay) + (az + aw);
        }
        __syncthreads();
        float* hf = (float*)hsm;
#pragma unroll
        for (int q = 0; q < 4; q++){
            int p = tid + 256*q;
            int s = p >> 6, j = p & 63;
            float gi = gsm[s*256 + j];
            float gf = gsm[s*256 + 64  + j];
            float gg = gsm[s*256 + 128 + j];
            float go = gsm[s*256 + 192 + j];
            float& c = (q == 0) ? c0 : (q == 1) ? c1 : (q == 2) ? c2 : c3;
            c = sigf(gf)*c + sigf(gi)*tanhacc(gg);
            hf[p] = sigf(go)*tanhacc(c);
        }
        __syncthreads();
    }
    const float* hf = (const float*)hsm;
#pragma unroll
    for (int q = 0; q < 4; q++){
        int p = tid + 256*q;
        int s = p >> 6, j = p & 63;
        g_lh[(size_t)(s0 + s)*Hh + j] = hf[p];
    }
}

// -------- K8: dual layernorm + sum + decoder (warp per (b,n)) --------
__global__ void k_final(const float* __restrict__ gg, const float* __restrict__ bg,
                        const float* __restrict__ gl, const float* __restrict__ bl,
                        const float* __restrict__ Wd, const float* __restrict__ bd,
                        float* __restrict__ out){
    int tid = threadIdx.x, lane = tid & 31;
    int r = (blockIdx.x * 256 + tid) >> 5;   // 0..2047
    // layernorm of g2 with (g_g, b_g)
    float x0 = g_g2[r*Hh + lane], x1 = g_g2[r*Hh + lane + 32];
    float mu = wsum(x0 + x1) * (1.f/64.f);
    float d0 = x0 - mu, d1 = x1 - mu;
    float var = wsum(d0*d0 + d1*d1) * (1.f/64.f);
    float rs = rsqrtf(var + 1e-5f);
    float n0 = d0*rs*gg[lane]      + bg[lane];
    float n1 = d1*rs*gg[lane + 32] + bg[lane + 32];
    // layernorm of lstm h with (g_l, b_l)
    float y0 = g_lh[r*Hh + lane], y1 = g_lh[r*Hh + lane + 32];
    float mu2 = wsum(y0 + y1) * (1.f/64.f);
    float e0 = y0 - mu2, e1 = y1 - mu2;
    float var2 = wsum(e0*e0 + e1*e1) * (1.f/64.f);
    float rs2 = rsqrtf(var2 + 1e-5f);
    float l0 = e0*rs2*gl[lane]      + bl[lane];
    float l1 = e1*rs2*gl[lane + 32] + bl[lane + 32];
    float t0 = n0 + l0, t1 = n1 + l1;
#pragma unroll
    for (int p = 0; p < PL; p++){
        float pp = t0*Wd[lane*PL + p] + t1*Wd[(lane + 32)*PL + p];
        pp = wsum(pp);
        if (lane == 0) out[r*PL + p] = pp + bd[p];
    }
}

extern "C" void kernel_launch(void* const* d_in, const int* in_sizes, int n_in,
                              void* d_out, int out_size){
    const float* x     = (const float*)d_in[0];
    const int*   ei    = (const int*)  d_in[1];
    const float* W_fc  = (const float*)d_in[2];
    const float* b_fc  = (const float*)d_in[3];
    const float* W1    = (const float*)d_in[4];
    const float* a_l1  = (const float*)d_in[5];
    const float* a_r1  = (const float*)d_in[6];
    const float* bias1 = (const float*)d_in[7];
    const float* W2    = (const float*)d_in[8];
    const float* a_l2  = (const float*)d_in[9];
    const float* a_r2  = (const float*)d_in[10];
    const float* bias2 = (const float*)d_in[11];
    const float* W_ih  = (const float*)d_in[12];
    const float* W_hh  = (const float*)d_in[13];
    const float* b_ih  = (const float*)d_in[14];
    const float* b_hh  = (const float*)d_in[15];
    const float* g_l   = (const float*)d_in[16];
    const float* b_l   = (const float*)d_in[17];
    const float* g_g   = (const float*)d_in[18];
    const float* b_g   = (const float*)d_in[19];
    const float* W_d   = (const float*)d_in[20];
    const float* b_d   = (const float*)d_in[21];
    float* out = (float*)d_out;

    int E = in_sizes[1] / 2;

    // adjacency: bitmask -> deduped CSR
    k_zero   <<<16, 512>>>();
    k_scatter<<<(E + 255) / 256, 256>>>(ei, E);
    k_nbr    <<<2, 256>>>();

    // x_h = x @ W_fc + b_fc (all t, needed by LSTM; t=T-1 slice feeds GAT)
    k_xh<<<XROWS / 8, 256>>>(x, W_fc, b_fc);

    // GAT layer 1 (t = T-1 only)
    k_gat_h  <<<MROWS / 8, 256>>>(W1, a_l1, a_r1, 0);
    k_gat_agg<<<MROWS / 8, 256>>>(bias1, 0);
    // GAT layer 2
    k_gat_h  <<<MROWS / 8, 256>>>(W2, a_l2, a_r2, 1);
    k_gat_agg<<<MROWS / 8, 256>>>(bias2, 1);

    // LSTM: input-gate GEMM precompute, then recurrence
    k_gx  <<<XROWS / 16, 256>>>(W_ih, b_ih, b_hh);
    k_lstm<<<MROWS / 16, 256>>>(W_hh);

    // layernorms + decoder
    k_final<<<MROWS / 8, 256>>>(g_g, b_g, g_l, b_l, W_d, b_d, out);
}

// round 12
// speedup vs baseline: 1.0004x; 1.0004x over previous
#include <cuda_runtime.h>
#include <math.h>

// Problem constants
#define Bq   4
#define Nn   512
#define Tt   24
#define NXf  8
#define Hh   64
#define PL   12
#define MAXD 128
#define MROWS (Bq*Nn)            // 2048 (b,n) rows
#define XROWS (Bq*Nn*Tt)         // 49152 (b,n,t) rows

// -------- scratch (device globals; no allocation allowed) --------
__device__ float    g_xh  [XROWS*Hh];        // x @ W_fc + b_fc, layout (b,n,t,h)
__device__ float    g_gx  [XROWS*4*Hh];      // precomputed input gates (row, 256)
__device__ float    g_hbuf[MROWS*Hh];        // GAT per-node features at t=T-1
__device__ float    g_el  [MROWS];
__device__ float    g_er  [MROWS];
__device__ float    g_g1  [MROWS*Hh];        // GAT layer-1 output (t=T-1 slice)
__device__ float    g_g2  [MROWS*Hh];        // GAT layer-2 output
__device__ float    g_lh  [MROWS*Hh];        // final LSTM hidden
__device__ unsigned g_bm  [Nn*16];           // adjacency bitmask (512 x 512 bits)
__device__ int      g_deg [Nn];
__device__ int      g_nbr [Nn*MAXD];

__device__ __forceinline__ float wsum(float v){
#pragma unroll
    for (int o = 16; o; o >>= 1) v += __shfl_xor_sync(0xffffffffu, v, o);
    return v;
}
__device__ __forceinline__ float wmax(float v){
#pragma unroll
    for (int o = 16; o; o >>= 1) v = fmaxf(v, __shfl_xor_sync(0xffffffffu, v, o));
    return v;
}
__device__ __forceinline__ float sigf(float x){ return 1.f / (1.f + __expf(-x)); }
__device__ __forceinline__ float tanhacc(float x){
    float e = __expf(2.f * x);
    return (e - 1.f) / (e + 1.f);
}

// -------- K0: zero bitmask --------
__global__ void k_zero(){
    int i = blockIdx.x * 512 + threadIdx.x;
    if (i < Nn*16) g_bm[i] = 0u;
}

// -------- K1: scatter edges into bitmask (dedup via OR) --------
__global__ void k_scatter(const int* __restrict__ ei, int E){
    int i = blockIdx.x * 256 + threadIdx.x;
    if (i >= E) return;
    int r = ei[i], c = ei[E + i];
    atomicOr(&g_bm[r*16 + (c >> 5)], 1u << (c & 31));
}

// -------- K2: bitmask -> compact neighbor lists --------
__global__ void k_nbr(){
    int m = blockIdx.x * 256 + threadIdx.x;
    if (m >= Nn) return;
    int cnt = 0;
#pragma unroll
    for (int w = 0; w < 16; w++){
        unsigned word = g_bm[m*16 + w];
        while (word){
            int b = __ffs(word) - 1;
            word &= word - 1;
            if (cnt < MAXD) g_nbr[m*MAXD + cnt] = w*32 + b;
            cnt++;
        }
    }
    g_deg[m] = cnt < MAXD ? cnt : MAXD;
}

// -------- K3: x_h = x @ W_fc + b_fc (warp per (b,n,t) row) --------
__global__ void k_xh(const float* __restrict__ x, const float* __restrict__ Wfc,
                     const float* __restrict__ bfc){
    __shared__ float wsm[NXf*Hh];
    __shared__ float bsm[Hh];
    int tid = threadIdx.x;
    for (int i = tid; i < NXf*Hh; i += 256) wsm[i] = Wfc[i];
    if (tid < Hh) bsm[tid] = bfc[tid];
    __syncthreads();
    int row  = (blockIdx.x * 256 + tid) >> 5;   // exact: 6144 blocks * 8 warps = 49152
    int lane = tid & 31;
    float xv = lane < NXf ? x[row*NXf + lane] : 0.f;
    float a0 = bsm[lane], a1 = bsm[lane + 32];
#pragma unroll
    for (int f = 0; f < NXf; f++){
        float v = __shfl_sync(0xffffffffu, xv, f);
        a0 = fmaf(v, wsm[f*Hh + lane],      a0);
        a1 = fmaf(v, wsm[f*Hh + lane + 32], a1);
    }
    g_xh[row*Hh + lane]      = a0;
    g_xh[row*Hh + lane + 32] = a1;
}

// -------- K4: GAT node transform at t=T-1: h = x @ W, el/er dots --------
__global__ void k_gat_h(const float* __restrict__ W, const float* __restrict__ al,
                        const float* __restrict__ ar, int layer){
    __shared__ float wsm[Hh*Hh];
    int tid = threadIdx.x;
    for (int i = tid; i < Hh*Hh; i += 256) wsm[i] = W[i];
    __syncthreads();
    int r    = (blockIdx.x * 256 + tid) >> 5;   // 0..2047 exact
    int lane = tid & 31;
    const float* xr = (layer == 0)
        ? (g_xh + (size_t)r * (Tt*Hh) + (Tt-1)*Hh)   // x_h[b,n,T-1,:]
        : (g_g1 + (size_t)r * Hh);                   // g1[b,n,T-1,:]
    float xa = xr[lane], xb = xr[lane + 32];
    float a0 = 0.f, a1 = 0.f;
#pragma unroll
    for (int f = 0; f < 32; f++){
        float v = __shfl_sync(0xffffffffu, xa, f);
        a0 = fmaf(v, wsm[f*Hh + lane],      a0);
        a1 = fmaf(v, wsm[f*Hh + lane + 32], a1);
    }
#pragma unroll
    for (int f = 0; f < 32; f++){
        float v = __shfl_sync(0xffffffffu, xb, f);
        a0 = fmaf(v, wsm[(f+32)*Hh + lane],      a0);
        a1 = fmaf(v, wsm[(f+32)*Hh + lane + 32], a1);
    }
    g_hbuf[r*Hh + lane]      = a0;
    g_hbuf[r*Hh + lane + 32] = a1;
    float pl = a0*al[lane] + a1*al[lane+32];
    float pr = a0*ar[lane] + a1*ar[lane+32];
    pl = wsum(pl); pr = wsum(pr);
    if (lane == 0){ g_el[r] = pl; g_er[r] = pr; }
}

// -------- K5: sparse GAT attention + aggregation + bias + exact GELU --------
__global__ void k_gat_agg(const float* __restrict__ bias, int layer){
    __shared__ float wbuf[8][MAXD];
    __shared__ int   nbuf[8][MAXD];
    int tid = threadIdx.x, lane = tid & 31, w = tid >> 5;
    int r = blockIdx.x * 8 + w;          // 0..2047
    int b = r >> 9, m = r & 511;
    int d = g_deg[m];
    float elm = g_el[r];
    float mx = -1e30f;
    for (int k = lane; k < d; k += 32){
        int n = g_nbr[m*MAXD + k];
        float e = elm + g_er[(b << 9) + n];
        e = e >= 0.f ? e : 0.2f * e;     // leaky_relu(0.2)
        wbuf[w][k] = e; nbuf[w][k] = n;
        mx = fmaxf(mx, e);
    }
    mx = wmax(mx);
    __syncwarp();
    float s = 0.f;
    for (int k = lane; k < d; k += 32){
        float wv = __expf(wbuf[w][k] - mx);
        wbuf[w][k] = wv; s += wv;
    }
    s = wsum(s);
    __syncwarp();
    float a0 = 0.f, a1 = 0.f;
    for (int k = 0; k < d; k++){
        float wv = wbuf[w][k];
        int   n  = nbuf[w][k];
        const float* hr = g_hbuf + ((size_t)((b << 9) + n)) * Hh;
        a0 = fmaf(wv, hr[lane],      a0);
        a1 = fmaf(wv, hr[lane + 32], a1);
    }
    float inv = 1.f / s;
    float v0 = a0*inv + bias[lane];
    float v1 = a1*inv + bias[lane+32];
    v0 = 0.5f * v0 * (1.f + erff(v0 * 0.70710678118654752f));   // exact gelu
    v1 = 0.5f * v1 * (1.f + erff(v1 * 0.70710678118654752f));
    float* out = layer ? g_g2 : g_g1;
    out[r*Hh + lane]      = v0;
    out[r*Hh + lane + 32] = v1;
}

// -------- K6: precompute input gates: gx = x_h @ W_ih^T + (b_ih + b_hh) ----
// 16 rows per block; thread g keeps W_ih[g][:] in registers; x broadcast smem.
__global__ void __launch_bounds__(256) k_gx(const float* __restrict__ Wih,
                                            const float* __restrict__ bih,
                                            const float* __restrict__ bhh){
    __shared__ float4 xs[16*16];   // 16 rows x 64 floats
    int tid  = threadIdx.x;        // = gate index g (0..255)
    int row0 = blockIdx.x * 16;
    xs[tid] = ((const float4*)(g_xh + (size_t)row0*Hh))[tid];
    float4 wreg[16];
#pragma unroll
    for (int j = 0; j < 16; j++) wreg[j] = ((const float4*)(Wih + tid*Hh))[j];
    float bsum = bih[tid] + bhh[tid];
    __syncthreads();
    float* gdst = g_gx + (size_t)row0*256 + tid;
#pragma unroll 4
    for (int rr = 0; rr < 16; rr++){
        const float4* xr = xs + rr*16;
        float ax = bsum, ay = 0.f, az = 0.f, aw = 0.f;
#pragma unroll
        for (int j = 0; j < 16; j++){
            float4 v = xr[j];
            ax = fmaf(v.x, wreg[j].x, ax);
            ay = fmaf(v.y, wreg[j].y, ay);
            az = fmaf(v.z, wreg[j].z, az);
            aw = fmaf(v.w, wreg[j].w, aw);
        }
        gdst[(size_t)rr*256] = (ax + ay) + (az + aw);
    }
}

// -------- K7: recurrent LSTM. 16 sequences per block, W_hh in registers ----
__global__ void __launch_bounds__(256) k_lstm(const float* __restrict__ Whh){
    __shared__ float4 hsm[16*16];      // 16 seq x 64 h
    __shared__ float  gsm[16*256];     // gate pre-activations
    int tid = threadIdx.x;             // = gate index g
    int s0  = blockIdx.x * 16;
    float4 wreg[16];
#pragma unroll
    for (int j = 0; j < 16; j++) wreg[j] = ((const float4*)(Whh + tid*Hh))[j];
    hsm[tid] = make_float4(0.f, 0.f, 0.f, 0.f);
    float c0 = 0.f, c1 = 0.f, c2 = 0.f, c3 = 0.f;
    __syncthreads();
    for (int t = 0; t < Tt; t++){
        const float* gxb = g_gx + ((size_t)s0*Tt + t)*256 + tid;
#pragma unroll 2
        for (int s = 0; s < 16; s++){
            const float4* hr = hsm + s*16;
            float ax = gxb[(size_t)s*Tt*256], ay = 0.f, az = 0.f, aw = 0.f;
#pragma unroll
            for (int j = 0; j < 16; j++){
                float4 v = hr[j];
                ax = fmaf(v.x, wreg[j].x, ax);
                ay = fmaf(v.y, wreg[j].y, ay);
                az = fmaf(v.z, wreg[j].z, az);
                aw = fmaf(v.w, wreg[j].w, aw);
            }
            gsm[s*256 + tid] = (ax + ay) + (az + aw);
        }
        __syncthreads();
        float* hf = (float*)hsm;
#pragma unroll
        for (int q = 0; q < 4; q++){
            int p = tid + 256*q;
            int s = p >> 6, j = p & 63;
            float gi = gsm[s*256 + j];
            float gf = gsm[s*256 + 64  + j];
            float gg = gsm[s*256 + 128 + j];
            float go = gsm[s*256 + 192 + j];
            float& c = (q == 0) ? c0 : (q == 1) ? c1 : (q == 2) ? c2 : c3;
            c = sigf(gf)*c + sigf(gi)*tanhacc(gg);
            hf[p] = sigf(go)*tanhacc(c);
        }
        __syncthreads();
    }
    const float* hf = (const float*)hsm;
#pragma unroll
    for (int q = 0; q < 4; q++){
        int p = tid + 256*q;
        int s = p >> 6, j = p & 63;
        g_lh[(size_t)(s0 + s)*Hh + j] = hf[p];
    }
}

// -------- K8: dual layernorm + sum + decoder (warp per (b,n)) --------
__global__ void k_final(const float* __restrict__ gg, const float* __restrict__ bg,
                        const float* __restrict__ gl, const float* __restrict__ bl,
                        const float* __restrict__ Wd, const float* __restrict__ bd,
                        float* __restrict__ out){
    int tid = threadIdx.x, lane = tid & 31;
    int r = (blockIdx.x * 256 + tid) >> 5;   // 0..2047
    // layernorm of g2 with (g_g, b_g)
    float x0 = g_g2[r*Hh + lane], x1 = g_g2[r*Hh + lane + 32];
    float mu = wsum(x0 + x1) * (1.f/64.f);
    float d0 = x0 - mu, d1 = x1 - mu;
    float var = wsum(d0*d0 + d1*d1) * (1.f/64.f);
    float rs = rsqrtf(var + 1e-5f);
    float n0 = d0*rs*gg[lane]      + bg[lane];
    float n1 = d1*rs*gg[lane + 32] + bg[lane + 32];
    // layernorm of lstm h with (g_l, b_l)
    float y0 = g_lh[r*Hh + lane], y1 = g_lh[r*Hh + lane + 32];
    float mu2 = wsum(y0 + y1) * (1.f/64.f);
    float e0 = y0 - mu2, e1 = y1 - mu2;
    float var2 = wsum(e0*e0 + e1*e1) * (1.f/64.f);
    float rs2 = rsqrtf(var2 + 1e-5f);
    float l0 = e0*rs2*gl[lane]      + bl[lane];
    float l1 = e1*rs2*gl[lane + 32] + bl[lane + 32];
    float t0 = n0 + l0, t1 = n1 + l1;
#pragma unroll
    for (int p = 0; p < PL; p++){
        float pp = t0*Wd[lane*PL + p] + t1*Wd[(lane + 32)*PL + p];
        pp = wsum(pp);
        if (lane == 0) out[r*PL + p] = pp + bd[p];
    }
}

extern "C" void kernel_launch(void* const* d_in, const int* in_sizes, int n_in,
                              void* d_out, int out_size){
    const float* x     = (const float*)d_in[0];
    const int*   ei    = (const int*)  d_in[1];
    const float* W_fc  = (const float*)d_in[2];
    const float* b_fc  = (const float*)d_in[3];
    const float* W1    = (const float*)d_in[4];
    const float* a_l1  = (const float*)d_in[5];
    const float* a_r1  = (const float*)d_in[6];
    const float* bias1 = (const float*)d_in[7];
    const float* W2    = (const float*)d_in[8];
    const float* a_l2  = (const float*)d_in[9];
    const float* a_r2  = (const float*)d_in[10];
    const float* bias2 = (const float*)d_in[11];
    const float* W_ih  = (const float*)d_in[12];
    const float* W_hh  = (const float*)d_in[13];
    const float* b_ih  = (const float*)d_in[14];
    const float* b_hh  = (const float*)d_in[15];
    const float* g_l   = (const float*)d_in[16];
    const float* b_l   = (const float*)d_in[17];
    const float* g_g   = (const float*)d_in[18];
    const float* b_g   = (const float*)d_in[19];
    const float* W_d   = (const float*)d_in[20];
    const float* b_d   = (const float*)d_in[21];
    float* out = (float*)d_out;

    int E = in_sizes[1] / 2;

    // adjacency: bitmask -> deduped CSR
    k_zero   <<<16, 512>>>();
    k_scatter<<<(E + 255) / 256, 256>>>(ei, E);
    k_nbr    <<<2, 256>>>();

    // x_h = x @ W_fc + b_fc (all t, needed by LSTM; t=T-1 slice feeds GAT)
    k_xh<<<XROWS / 8, 256>>>(x, W_fc, b_fc);

    // GAT layer 1 (t = T-1 only)
    k_gat_h  <<<MROWS / 8, 256>>>(W1, a_l1, a_r1, 0);
    k_gat_agg<<<MROWS / 8, 256>>>(bias1, 0);
    // GAT layer 2
    k_gat_h  <<<MROWS / 8, 256>>>(W2, a_l2, a_r2, 1);
    k_gat_agg<<<MROWS / 8, 256>>>(bias2, 1);

    // LSTM: input-gate GEMM precompute, then recurrence
    k_gx  <<<XROWS / 16, 256>>>(W_ih, b_ih, b_hh);
    k_lstm<<<MROWS / 16, 256>>>(W_hh);

    // layernorms + decoder
    k_final<<<MROWS / 8, 256>>>(g_g, b_g, g_l, b_l, W_d, b_d, out);
}